// round 15
// baseline (speedup 1.0000x reference)
#include <cuda_runtime.h>
#include <cuda_fp16.h>

#define GRIDSZ 160
#define GRID3 (GRIDSZ*GRIDSZ*GRIDSZ)
#define NPTS 262144
#define CIN 64
#define COUT 96
#define TILE 64
#define TILES_PER_K 4096
#define LN_EPS 1e-5f
#define MAX_TILES (27 * TILES_PER_K)

// A smem row stride (words): 32 + 4 pad (36%32==4 -> conflict-free pattern)
#define RWA 36
// B smem row stride (words): 32 + 4 pad
#define RWB 36

// ---------------- scratch (static device globals; no allocation) ----------------
__device__ int    g_grid[GRID3];
__device__ int    g_win[NPTS];
__device__ int    g_cnt[27];
__device__ int2   g_pairs[27u * NPTS];
__device__ float  g_conv[(size_t)NPTS * COUT];
__device__ __half g_wprep[27 * 96 * 64];            // [k][n][cin], fp16, n-major
__device__ __half g_feat16[(size_t)NPTS * 64];      // fp16 features (single plane)
__device__ int    g_ntiles;
__device__ int2   g_tiles[MAX_TILES];               // (k, row_base)

// ---------------- helpers --------------------------------------------------------
__device__ __forceinline__ void mma16816h(float* c, unsigned a0, unsigned a1,
                                          unsigned a2, unsigned a3,
                                          unsigned b0, unsigned b1) {
    asm volatile(
        "mma.sync.aligned.m16n8k16.row.col.f32.f16.f16.f32 "
        "{%0,%1,%2,%3}, {%4,%5,%6,%7}, {%8,%9}, {%0,%1,%2,%3};"
        : "+f"(c[0]), "+f"(c[1]), "+f"(c[2]), "+f"(c[3])
        : "r"(a0), "r"(a1), "r"(a2), "r"(a3), "r"(b0), "r"(b1));
}

__device__ __forceinline__ void red_add4(float* addr, float a, float b, float c, float d) {
    asm volatile("red.global.add.v4.f32 [%0], {%1, %2, %3, %4};"
                 :: "l"(addr), "f"(a), "f"(b), "f"(c), "f"(d) : "memory");
}

// cp.async 16B, .cg (bypass L1), predicated size (0 -> zfill)
__device__ __forceinline__ void cp16(unsigned daddr, const void* src, int szbytes) {
    asm volatile("cp.async.cg.shared.global [%0], [%1], 16, %2;"
                 :: "r"(daddr), "l"(src), "r"(szbytes));
}
__device__ __forceinline__ void cp_commit() {
    asm volatile("cp.async.commit_group;");
}
template<int N> __device__ __forceinline__ void cp_wait() {
    asm volatile("cp.async.wait_group %0;" :: "n"(N));
}

// ---------------- 1) init grid to -1, zero counters ------------------------------
__global__ void k_init() {
    int tid = blockIdx.x * blockDim.x + threadIdx.x;
    if (tid < 27) g_cnt[tid] = 0;
    int4* g4 = (int4*)g_grid;
    const int n4 = GRID3 / 4;
    const int stride = gridDim.x * blockDim.x;
    int4 m1 = make_int4(-1, -1, -1, -1);
    for (int i = tid; i < n4; i += stride) g4[i] = m1;
}

// ---------------- 2) scatter (last-write-wins via atomicMax) ---------------------
__global__ void k_scatter(const int* __restrict__ coords) {
    int i = blockIdx.x * blockDim.x + threadIdx.x;
    if (i < NPTS) {
        int z = coords[3*i+0], y = coords[3*i+1], x = coords[3*i+2];
        atomicMax(&g_grid[(z*GRIDSZ + y)*GRIDSZ + x], i);
    }
}

// ---------------- 3) prep: weights fp16 n-major + features fp16 ------------------
__global__ void k_prep(const float* __restrict__ w, const float* __restrict__ feats) {
    const int t = blockIdx.x * 256 + threadIdx.x;
    if (t < NPTS * 16) {
        float4 v = ((const float4*)feats)[t];
        __half2* dst = (__half2*)(g_feat16 + (size_t)t * 4);
        dst[0] = __floats2half2_rn(v.x, v.y);
        dst[1] = __floats2half2_rn(v.z, v.w);
    }
    if (t < 27 * CIN * COUT) {
        const int k = t / (CIN * COUT);
        const int r = t % (CIN * COUT);
        const int c = r / COUT;
        const int n = r % COUT;
        g_wprep[(k * 96 + n) * 64 + c] = __float2half_rn(w[t]);
    }
}

// ---------------- 4) symmetric pair build: winners probe 13 forward offsets ------
__global__ __launch_bounds__(256) void k_build_pairs(const int* __restrict__ coords) {
    __shared__ int s_cnt[13][8];
    __shared__ int s_baseF[13][8];
    __shared__ int s_baseM[13][8];

    const int tid  = threadIdx.x;
    const int p    = blockIdx.x * 256 + tid;
    const int warp = tid >> 5, lane = tid & 31;

    const int z = coords[3*p+0], y = coords[3*p+1], x = coords[3*p+2];
    const int cell = (z*GRIDSZ + y)*GRIDSZ + x;
    const int c = g_grid[cell];
    g_win[p] = c;
    const bool winner = (c == p);

    int nidx[13];
    #pragma unroll
    for (int k = 0; k < 13; ++k) {
        const int dz = k/9 - 1, dy = (k/3)%3 - 1, dx = k%3 - 1;
        int zz = z + dz, yy = y + dy, xx = x + dx;
        int ni = -1;
        if (winner && (unsigned)zz < GRIDSZ && (unsigned)yy < GRIDSZ && (unsigned)xx < GRIDSZ)
            ni = g_grid[(zz*GRIDSZ + yy)*GRIDSZ + xx];
        nidx[k] = ni;
    }

    #pragma unroll
    for (int k = 0; k < 13; ++k) {
        unsigned m = __ballot_sync(0xffffffffu, nidx[k] >= 0);
        if (lane == 0) s_cnt[k][warp] = __popc(m);
    }
    __syncthreads();

    if (tid < 13) {
        int cw[8], tot = 0;
        #pragma unroll
        for (int w = 0; w < 8; ++w) { cw[w] = s_cnt[tid][w]; tot += cw[w]; }
        int bF = tot ? atomicAdd(&g_cnt[tid],      tot) : 0;
        int bM = tot ? atomicAdd(&g_cnt[26 - tid], tot) : 0;
        #pragma unroll
        for (int w = 0; w < 8; ++w) {
            s_baseF[tid][w] = bF; bF += cw[w];
            s_baseM[tid][w] = bM; bM += cw[w];
        }
    }
    __syncthreads();

    #pragma unroll
    for (int k = 0; k < 13; ++k) {
        unsigned m = __ballot_sync(0xffffffffu, nidx[k] >= 0);
        if (nidx[k] >= 0) {
            int rank = __popc(m & ((1u << lane) - 1u));
            g_pairs[k * NPTS      + s_baseF[k][warp] + rank] = make_int2(p, nidx[k]);
            g_pairs[(26-k) * NPTS + s_baseM[k][warp] + rank] = make_int2(nidx[k], p);
        }
    }
}

// ---------------- 5) flatten non-empty tiles into a descriptor list ---------------
__global__ void k_make_tiles() {
    __shared__ int s_off[28];
    const int tid = threadIdx.x;
    if (tid < 32) {
        int cnt = (tid < 27) ? g_cnt[tid] : 0;
        int nt  = (cnt + TILE - 1) >> 6;
        int inc = nt;
        #pragma unroll
        for (int o = 1; o < 32; o <<= 1) {
            int v = __shfl_up_sync(0xffffffffu, inc, o);
            if (tid >= o) inc += v;
        }
        if (tid < 27) s_off[tid + 1] = inc;
        if (tid == 0) s_off[0] = 0;
        if (tid == 26) g_ntiles = inc;
    }
    __syncthreads();
    const int total = s_off[27];
    for (int t = tid; t < total; t += blockDim.x) {
        int k = 0;
        while (s_off[k + 1] <= t) ++k;
        g_tiles[t] = make_int2(k, (t - s_off[k]) * TILE);
    }
}

// ======================= shared GEMM-tile machinery (256 thr, 64-row tile) =======
// cp.async gather: 2x16B per thread from fp16 feature table; zfill when invalid.
__device__ __forceinline__ void gather_A_cp(unsigned sA, int ni, int tid) {
    const int row = tid >> 2, q = tid & 3;
    const unsigned d = sA + (row * RWA + q * 8) * 4;
    const char* src = (const char*)(g_feat16 + (size_t)(ni >= 0 ? ni : 0) * 64) + q * 32;
    const int sz = (ni >= 0) ? 16 : 0;
    cp16(d,      src,      sz);
    cp16(d + 16, src + 16, sz);
}

__device__ __forceinline__ void load_B_cp(unsigned sB, int k, int tid) {
    const char* src = (const char*)&g_wprep[(size_t)k * 96 * 64];
    #pragma unroll
    for (int it = 0; it < 3; ++it) {
        int i = tid + it * 256;          // 0..767 (16B units)
        int n = i >> 3, q = i & 7;
        cp16(sB + (n * RWB + q * 4) * 4, src + i * 16, 16);
    }
}

__device__ __forceinline__ void mma_mainloop(const unsigned* sAw, const unsigned* sBw,
                                             float acc[6][4], int lane, int wm, int wn) {
    const int g = lane >> 2, tg = lane & 3;
    const int r0 = wm * 16 + g, r1 = r0 + 8;
    #pragma unroll
    for (int kb = 0; kb < 4; ++kb) {
        const int kw = kb * 8 + tg;
        const unsigned a0 = sAw[r0 * RWA + kw],     a1 = sAw[r1 * RWA + kw];
        const unsigned a2 = sAw[r0 * RWA + kw + 4], a3 = sAw[r1 * RWA + kw + 4];
        #pragma unroll
        for (int nb = 0; nb < 6; ++nb) {
            const int n = wn * 48 + nb * 8 + g;
            const unsigned b0 = sBw[n * RWB + kw], b1 = sBw[n * RWB + kw + 4];
            mma16816h(acc[nb], a0, a1, a2, a3, b0, b1);
        }
    }
}

// ---------------- 6) center tap: dense GEMM, cp.async loads, float4 stores --------
// Launched 4th so ncu (-s 5 -c 1 captures it) profiles this kernel.
__global__ __launch_bounds__(256, 5) void k_center_gemm(const int* __restrict__ coords,
                                                        const float* __restrict__ bias) {
    __shared__ unsigned sAw[64 * RWA];
    __shared__ unsigned sBw[96 * RWB];

    const int tid  = threadIdx.x;
    const int base = blockIdx.x * TILE;
    const unsigned sa = (unsigned)__cvta_generic_to_shared(sAw);
    const unsigned sb = (unsigned)__cvta_generic_to_shared(sBw);

    {
        const int p = base + (tid >> 2);
        const int z = coords[3*p+0], y = coords[3*p+1], x = coords[3*p+2];
        const int ni = g_grid[(z*GRIDSZ + y)*GRIDSZ + x];   // winner (collision-aware)
        gather_A_cp(sa, ni, tid);
    }
    load_B_cp(sb, 13, tid);
    cp_commit();
    cp_wait<0>();
    __syncthreads();

    const int lane = tid & 31, wid = tid >> 5;
    const int wm = wid & 3, wn = wid >> 2;
    float acc[6][4];
    #pragma unroll
    for (int nb = 0; nb < 6; ++nb)
        #pragma unroll
        for (int c = 0; c < 4; ++c) acc[nb][c] = 0.f;

    mma_mainloop(sAw, sBw, acc, lane, wm, wn);

    const int g = lane >> 2, tg = lane & 3;
    const bool ev = (tg & 1) == 0;
    const int row0 = base + wm * 16 + g, row1 = row0 + 8;
    #pragma unroll
    for (int nb = 0; nb < 6; ++nb) {
        float s0 = ev ? acc[nb][2] : acc[nb][0];
        float s1 = ev ? acc[nb][3] : acc[nb][1];
        float r0 = __shfl_xor_sync(0xffffffffu, s0, 1);
        float r1 = __shfl_xor_sync(0xffffffffu, s1, 1);
        const int cb = wn * 48 + nb * 8 + (ev ? 2 * tg : 2 * (tg - 1));
        float4 b4 = *(const float4*)(bias + cb);
        if (ev) {
            *(float4*)(g_conv + (size_t)row0 * COUT + cb) =
                make_float4(acc[nb][0] + b4.x, acc[nb][1] + b4.y, r0 + b4.z, r1 + b4.w);
        } else {
            *(float4*)(g_conv + (size_t)row1 * COUT + cb) =
                make_float4(r0 + b4.x, r1 + b4.y, acc[nb][2] + b4.z, acc[nb][3] + b4.w);
        }
    }
}

// ---------------- 7) non-center taps: tile-list GEMM, cp.async loads --------------
__global__ __launch_bounds__(256, 5) void k_offset_gemm() {
    __shared__ unsigned sAw[64 * RWA];
    __shared__ unsigned sBw[96 * RWB];

    const int tid   = threadIdx.x;
    const int lane  = tid & 31, wid = tid >> 5;
    const int wm    = wid & 3,  wn  = wid >> 2;
    const int total = g_ntiles;
    const unsigned sa = (unsigned)__cvta_generic_to_shared(sAw);
    const unsigned sb = (unsigned)__cvta_generic_to_shared(sBw);

    for (int t = blockIdx.x; t < total; t += gridDim.x) {
        const int2 td    = g_tiles[t];
        const int  k     = td.x;
        const int  rbase = td.y;
        const int  cnt   = g_cnt[k];

        {
            const int i = rbase + (tid >> 2);
            const int ni = (i < cnt) ? g_pairs[k * NPTS + i].y : -1;
            gather_A_cp(sa, ni, tid);
        }
        load_B_cp(sb, k, tid);
        cp_commit();
        cp_wait<0>();
        __syncthreads();

        float acc[6][4];
        #pragma unroll
        for (int nb = 0; nb < 6; ++nb)
            #pragma unroll
            for (int c = 0; c < 4; ++c) acc[nb][c] = 0.f;

        mma_mainloop(sAw, sBw, acc, lane, wm, wn);

        const int g = lane >> 2, tg = lane & 3;
        const bool ev = (tg & 1) == 0;
        const int i0 = rbase + wm * 16 + g, i1 = i0 + 8;
        const int op0 = (i0 < cnt) ? g_pairs[k * NPTS + i0].x : -1;
        const int op1 = (i1 < cnt) ? g_pairs[k * NPTS + i1].x : -1;
        #pragma unroll
        for (int nb = 0; nb < 6; ++nb) {
            float s0 = ev ? acc[nb][2] : acc[nb][0];
            float s1 = ev ? acc[nb][3] : acc[nb][1];
            float r0 = __shfl_xor_sync(0xffffffffu, s0, 1);
            float r1 = __shfl_xor_sync(0xffffffffu, s1, 1);
            const int cb = wn * 48 + nb * 8 + (ev ? 2 * tg : 2 * (tg - 1));
            if (ev) {
                if (op0 >= 0)
                    red_add4(g_conv + (size_t)op0 * COUT + cb,
                             acc[nb][0], acc[nb][1], r0, r1);
            } else {
                if (op1 >= 0)
                    red_add4(g_conv + (size_t)op1 * COUT + cb,
                             r0, r1, acc[nb][2], acc[nb][3]);
            }
        }
        __syncthreads();   // protect smem before next tile's gather
    }
}

// ---------------- 8) LayerNorm + ReLU (winner-row indirection) --------------------
__global__ __launch_bounds__(256) void k_ln_relu(const float* __restrict__ gamma,
                                                 const float* __restrict__ beta,
                                                 float* __restrict__ out) {
    const int row  = (blockIdx.x * 256 + threadIdx.x) >> 5;
    const int lane = threadIdx.x & 31;
    const int src_row = g_win[row];
    const float* src = g_conv + (size_t)src_row * COUT;
    float v0 = src[lane], v1 = src[lane + 32], v2 = src[lane + 64];
    float s  = v0 + v1 + v2;
    float sq = v0*v0 + v1*v1 + v2*v2;
    #pragma unroll
    for (int o = 16; o > 0; o >>= 1) {
        s  += __shfl_xor_sync(0xffffffffu, s,  o);
        sq += __shfl_xor_sync(0xffffffffu, sq, o);
    }
    float mean = s * (1.f / COUT);
    float var  = sq * (1.f / COUT) - mean * mean;
    float inv  = rsqrtf(var + LN_EPS);
    float* dst = out + (size_t)row * COUT;
    dst[lane]      = fmaxf((v0 - mean) * inv * gamma[lane]      + beta[lane],      0.f);
    dst[lane + 32] = fmaxf((v1 - mean) * inv * gamma[lane + 32] + beta[lane + 32], 0.f);
    dst[lane + 64] = fmaxf((v2 - mean) * inv * gamma[lane + 64] + beta[lane + 64], 0.f);
}

// ---------------- launch ----------------------------------------------------------
extern "C" void kernel_launch(void* const* d_in, const int* in_sizes, int n_in,
                              void* d_out, int out_size) {
    const float* feats  = (const float*)d_in[0];
    const int*   coords = (const int*)  d_in[1];
    const float* weight = (const float*)d_in[2];
    const float* bias   = (const float*)d_in[3];
    const float* gamma  = (const float*)d_in[4];
    const float* beta   = (const float*)d_in[5];
    float* out = (float*)d_out;

    k_init       <<<4096, 256>>>();
    k_scatter    <<<NPTS / 256, 256>>>(coords);
    k_prep       <<<NPTS * 16 / 256, 256>>>(weight, feats);
    k_center_gemm<<<TILES_PER_K, 256>>>(coords, bias);   // 4th: ncu profiles this
    k_build_pairs<<<NPTS / 256, 256>>>(coords);
    k_make_tiles <<<1, 256>>>();
    k_offset_gemm<<<8192, 256>>>();
    k_ln_relu    <<<NPTS / 8, 256>>>(gamma, beta, out);
}

// round 16
// speedup vs baseline: 1.0328x; 1.0328x over previous
#include <cuda_runtime.h>
#include <cuda_fp16.h>

#define GRIDSZ 160
#define GRID3 (GRIDSZ*GRIDSZ*GRIDSZ)
#define NPTS 262144
#define CIN 64
#define COUT 96
#define TILE 64
#define TILES_PER_K 4096
#define LN_EPS 1e-5f
#define MAX_TILES (27 * TILES_PER_K)

// A smem row stride (words): 32 + 4 pad (36%32==4 -> conflict-free pattern)
#define RWA 36
// B smem row stride (words): 32 + 4 pad
#define RWB 36

// ---------------- scratch (static device globals; no allocation) ----------------
__device__ int    g_grid[GRID3];
__device__ int    g_win[NPTS];
__device__ int    g_cnt[27];
__device__ int2   g_pairs[27u * NPTS];
__device__ float  g_conv[(size_t)NPTS * COUT];
__device__ __half g_wprep[27 * 96 * 64];            // [k][n][cin], fp16, n-major
__device__ __half g_feat16[(size_t)NPTS * 64];      // fp16 features (single plane)
__device__ int    g_ntiles;
__device__ int2   g_tiles[MAX_TILES];               // (k, row_base)

// ---------------- helpers --------------------------------------------------------
__device__ __forceinline__ void mma16816h(float* c, unsigned a0, unsigned a1,
                                          unsigned a2, unsigned a3,
                                          unsigned b0, unsigned b1) {
    asm volatile(
        "mma.sync.aligned.m16n8k16.row.col.f32.f16.f16.f32 "
        "{%0,%1,%2,%3}, {%4,%5,%6,%7}, {%8,%9}, {%0,%1,%2,%3};"
        : "+f"(c[0]), "+f"(c[1]), "+f"(c[2]), "+f"(c[3])
        : "r"(a0), "r"(a1), "r"(a2), "r"(a3), "r"(b0), "r"(b1));
}

__device__ __forceinline__ void red_add4(float* addr, float a, float b, float c, float d) {
    asm volatile("red.global.add.v4.f32 [%0], {%1, %2, %3, %4};"
                 :: "l"(addr), "f"(a), "f"(b), "f"(c), "f"(d) : "memory");
}

// ---------------- 1) init grid to -1 ----------------------------------------------
__global__ void k_init() {
    int tid = blockIdx.x * blockDim.x + threadIdx.x;
    int4* g4 = (int4*)g_grid;
    const int n4 = GRID3 / 4;
    const int stride = gridDim.x * blockDim.x;
    int4 m1 = make_int4(-1, -1, -1, -1);
    for (int i = tid; i < n4; i += stride) g4[i] = m1;
}

// ---------------- 2) scatter (last-write-wins via atomicMax) + zero counters -----
__global__ void k_scatter(const int* __restrict__ coords) {
    int i = blockIdx.x * blockDim.x + threadIdx.x;
    if (blockIdx.x == 0 && threadIdx.x < 27) g_cnt[threadIdx.x] = 0;
    if (i < NPTS) {
        int z = coords[3*i+0], y = coords[3*i+1], x = coords[3*i+2];
        atomicMax(&g_grid[(z*GRIDSZ + y)*GRIDSZ + x], i);
    }
}

// ---------------- 3) prep: weights fp16 n-major + features fp16 ------------------
__global__ void k_prep(const float* __restrict__ w, const float* __restrict__ feats) {
    const int t = blockIdx.x * 256 + threadIdx.x;
    if (t < NPTS * 16) {
        float4 v = ((const float4*)feats)[t];
        __half2* dst = (__half2*)(g_feat16 + (size_t)t * 4);
        dst[0] = __floats2half2_rn(v.x, v.y);
        dst[1] = __floats2half2_rn(v.z, v.w);
    }
    if (t < 27 * CIN * COUT) {
        const int k = t / (CIN * COUT);
        const int r = t % (CIN * COUT);
        const int c = r / COUT;
        const int n = r % COUT;
        g_wprep[(k * 96 + n) * 64 + c] = __float2half_rn(w[t]);
    }
}

// ---------------- 4) symmetric pair build: winners probe 13 forward offsets ------
__global__ __launch_bounds__(256) void k_build_pairs(const int* __restrict__ coords) {
    __shared__ int s_cnt[13][8];
    __shared__ int s_baseF[13][8];
    __shared__ int s_baseM[13][8];

    const int tid  = threadIdx.x;
    const int p    = blockIdx.x * 256 + tid;
    const int warp = tid >> 5, lane = tid & 31;

    const int z = coords[3*p+0], y = coords[3*p+1], x = coords[3*p+2];
    const int cell = (z*GRIDSZ + y)*GRIDSZ + x;
    const int c = g_grid[cell];
    g_win[p] = c;
    const bool winner = (c == p);

    int nidx[13];
    #pragma unroll
    for (int k = 0; k < 13; ++k) {
        const int dz = k/9 - 1, dy = (k/3)%3 - 1, dx = k%3 - 1;
        int zz = z + dz, yy = y + dy, xx = x + dx;
        int ni = -1;
        if (winner && (unsigned)zz < GRIDSZ && (unsigned)yy < GRIDSZ && (unsigned)xx < GRIDSZ)
            ni = g_grid[(zz*GRIDSZ + yy)*GRIDSZ + xx];
        nidx[k] = ni;
    }

    #pragma unroll
    for (int k = 0; k < 13; ++k) {
        unsigned m = __ballot_sync(0xffffffffu, nidx[k] >= 0);
        if (lane == 0) s_cnt[k][warp] = __popc(m);
    }
    __syncthreads();

    if (tid < 13) {
        int cw[8], tot = 0;
        #pragma unroll
        for (int w = 0; w < 8; ++w) { cw[w] = s_cnt[tid][w]; tot += cw[w]; }
        int bF = tot ? atomicAdd(&g_cnt[tid],      tot) : 0;
        int bM = tot ? atomicAdd(&g_cnt[26 - tid], tot) : 0;
        #pragma unroll
        for (int w = 0; w < 8; ++w) {
            s_baseF[tid][w] = bF; bF += cw[w];
            s_baseM[tid][w] = bM; bM += cw[w];
        }
    }
    __syncthreads();

    #pragma unroll
    for (int k = 0; k < 13; ++k) {
        unsigned m = __ballot_sync(0xffffffffu, nidx[k] >= 0);
        if (nidx[k] >= 0) {
            int rank = __popc(m & ((1u << lane) - 1u));
            g_pairs[k * NPTS      + s_baseF[k][warp] + rank] = make_int2(p, nidx[k]);
            g_pairs[(26-k) * NPTS + s_baseM[k][warp] + rank] = make_int2(nidx[k], p);
        }
    }
}

// ---------------- 5) flatten non-empty tiles into a descriptor list ---------------
__global__ void k_make_tiles() {
    __shared__ int s_off[28];
    const int tid = threadIdx.x;
    if (tid < 32) {
        int cnt = (tid < 27) ? g_cnt[tid] : 0;
        int nt  = (cnt + TILE - 1) >> 6;
        int inc = nt;
        #pragma unroll
        for (int o = 1; o < 32; o <<= 1) {
            int v = __shfl_up_sync(0xffffffffu, inc, o);
            if (tid >= o) inc += v;
        }
        if (tid < 27) s_off[tid + 1] = inc;
        if (tid == 0) s_off[0] = 0;
        if (tid == 26) g_ntiles = inc;
    }
    __syncthreads();
    const int total = s_off[27];
    for (int t = tid; t < total; t += blockDim.x) {
        int k = 0;
        while (s_off[k + 1] <= t) ++k;
        g_tiles[t] = make_int2(k, (t - s_off[k]) * TILE);
    }
}

// ======================= shared GEMM-tile machinery (256 thr, 64-row tile) =======
// Direct gather from fp16 table: each thread copies 32B (2 x uint4), no converts.
__device__ __forceinline__ void gather_A_direct(unsigned* sAw, int ni, int tid) {
    const int row = tid >> 2, q = tid & 3;
    unsigned* d = &sAw[row * RWA + q * 8];
    if (ni >= 0) {
        const uint4* src = (const uint4*)(g_feat16 + (size_t)ni * 64) + q * 2;
        uint4 v0 = src[0], v1 = src[1];
        *(uint4*)(d)     = v0;
        *(uint4*)(d + 4) = v1;
    } else {
        uint4 z4 = make_uint4(0u, 0u, 0u, 0u);
        *(uint4*)(d)     = z4;
        *(uint4*)(d + 4) = z4;
    }
}

__device__ __forceinline__ void load_B(unsigned* sBw, int k, int tid) {
    const uint4* src = (const uint4*)&g_wprep[(size_t)k * 96 * 64];
    #pragma unroll
    for (int it = 0; it < 3; ++it) {
        int i = tid + it * 256;
        int n = i >> 3, q = i & 7;
        *(uint4*)&sBw[n * RWB + q * 4] = src[i];
    }
}

__device__ __forceinline__ void mma_mainloop(const unsigned* sAw, const unsigned* sBw,
                                             float acc[6][4], int lane, int wm, int wn) {
    const int g = lane >> 2, tg = lane & 3;
    const int r0 = wm * 16 + g, r1 = r0 + 8;
    #pragma unroll
    for (int kb = 0; kb < 4; ++kb) {
        const int kw = kb * 8 + tg;
        const unsigned a0 = sAw[r0 * RWA + kw],     a1 = sAw[r1 * RWA + kw];
        const unsigned a2 = sAw[r0 * RWA + kw + 4], a3 = sAw[r1 * RWA + kw + 4];
        #pragma unroll
        for (int nb = 0; nb < 6; ++nb) {
            const int n = wn * 48 + nb * 8 + g;
            const unsigned b0 = sBw[n * RWB + kw], b1 = sBw[n * RWB + kw + 4];
            mma16816h(acc[nb], a0, a1, a2, a3, b0, b1);
        }
    }
}

// ---------------- 6) center tap: dense GEMM, one barrier, float4 stores -----------
// Launched 4th so ncu (-s 5 -c 1 captures it) profiles this kernel.
__global__ __launch_bounds__(256, 6) void k_center_gemm(const int* __restrict__ coords,
                                                        const float* __restrict__ bias) {
    __shared__ unsigned sAw[64 * RWA];
    __shared__ unsigned sBw[96 * RWB];

    const int tid  = threadIdx.x;
    const int base = blockIdx.x * TILE;

    {
        const int p = base + (tid >> 2);
        const int z = coords[3*p+0], y = coords[3*p+1], x = coords[3*p+2];
        const int ni = g_grid[(z*GRIDSZ + y)*GRIDSZ + x];   // winner (collision-aware)
        gather_A_direct(sAw, ni, tid);
    }
    load_B(sBw, 13, tid);
    __syncthreads();

    const int lane = tid & 31, wid = tid >> 5;
    const int wm = wid & 3, wn = wid >> 2;
    float acc[6][4];
    #pragma unroll
    for (int nb = 0; nb < 6; ++nb)
        #pragma unroll
        for (int c = 0; c < 4; ++c) acc[nb][c] = 0.f;

    mma_mainloop(sAw, sBw, acc, lane, wm, wn);

    const int g = lane >> 2, tg = lane & 3;
    const bool ev = (tg & 1) == 0;
    const int row0 = base + wm * 16 + g, row1 = row0 + 8;
    #pragma unroll
    for (int nb = 0; nb < 6; ++nb) {
        float s0 = ev ? acc[nb][2] : acc[nb][0];
        float s1 = ev ? acc[nb][3] : acc[nb][1];
        float r0 = __shfl_xor_sync(0xffffffffu, s0, 1);
        float r1 = __shfl_xor_sync(0xffffffffu, s1, 1);
        const int cb = wn * 48 + nb * 8 + (ev ? 2 * tg : 2 * (tg - 1));
        float4 b4 = *(const float4*)(bias + cb);
        if (ev) {
            *(float4*)(g_conv + (size_t)row0 * COUT + cb) =
                make_float4(acc[nb][0] + b4.x, acc[nb][1] + b4.y, r0 + b4.z, r1 + b4.w);
        } else {
            *(float4*)(g_conv + (size_t)row1 * COUT + cb) =
                make_float4(r0 + b4.x, r1 + b4.y, acc[nb][2] + b4.z, acc[nb][3] + b4.w);
        }
    }
}

// ---------------- 7) non-center taps: tile-list GEMM, 2 barriers/tile -------------
__global__ __launch_bounds__(256, 6) void k_offset_gemm() {
    __shared__ unsigned sAw[64 * RWA];
    __shared__ unsigned sBw[96 * RWB];

    const int tid   = threadIdx.x;
    const int lane  = tid & 31, wid = tid >> 5;
    const int wm    = wid & 3,  wn  = wid >> 2;
    const int total = g_ntiles;

    for (int t = blockIdx.x; t < total; t += gridDim.x) {
        const int2 td    = g_tiles[t];
        const int  k     = td.x;
        const int  rbase = td.y;
        const int  cnt   = g_cnt[k];

        {
            const int i = rbase + (tid >> 2);
            const int ni = (i < cnt) ? g_pairs[k * NPTS + i].y : -1;
            gather_A_direct(sAw, ni, tid);
        }
        load_B(sBw, k, tid);
        __syncthreads();

        float acc[6][4];
        #pragma unroll
        for (int nb = 0; nb < 6; ++nb)
            #pragma unroll
            for (int c = 0; c < 4; ++c) acc[nb][c] = 0.f;

        mma_mainloop(sAw, sBw, acc, lane, wm, wn);

        const int g = lane >> 2, tg = lane & 3;
        const bool ev = (tg & 1) == 0;
        const int i0 = rbase + wm * 16 + g, i1 = i0 + 8;
        const int op0 = (i0 < cnt) ? g_pairs[k * NPTS + i0].x : -1;
        const int op1 = (i1 < cnt) ? g_pairs[k * NPTS + i1].x : -1;
        #pragma unroll
        for (int nb = 0; nb < 6; ++nb) {
            float s0 = ev ? acc[nb][2] : acc[nb][0];
            float s1 = ev ? acc[nb][3] : acc[nb][1];
            float r0 = __shfl_xor_sync(0xffffffffu, s0, 1);
            float r1 = __shfl_xor_sync(0xffffffffu, s1, 1);
            const int cb = wn * 48 + nb * 8 + (ev ? 2 * tg : 2 * (tg - 1));
            if (ev) {
                if (op0 >= 0)
                    red_add4(g_conv + (size_t)op0 * COUT + cb,
                             acc[nb][0], acc[nb][1], r0, r1);
            } else {
                if (op1 >= 0)
                    red_add4(g_conv + (size_t)op1 * COUT + cb,
                             r0, r1, acc[nb][2], acc[nb][3]);
            }
        }
        __syncthreads();   // protect smem before next tile's gather
    }
}

// ---------------- 8) LayerNorm + ReLU (winner-row indirection) --------------------
__global__ __launch_bounds__(256) void k_ln_relu(const float* __restrict__ gamma,
                                                 const float* __restrict__ beta,
                                                 float* __restrict__ out) {
    const int row  = (blockIdx.x * 256 + threadIdx.x) >> 5;
    const int lane = threadIdx.x & 31;
    const int src_row = g_win[row];
    const float* src = g_conv + (size_t)src_row * COUT;
    float v0 = src[lane], v1 = src[lane + 32], v2 = src[lane + 64];
    float s  = v0 + v1 + v2;
    float sq = v0*v0 + v1*v1 + v2*v2;
    #pragma unroll
    for (int o = 16; o > 0; o >>= 1) {
        s  += __shfl_xor_sync(0xffffffffu, s,  o);
        sq += __shfl_xor_sync(0xffffffffu, sq, o);
    }
    float mean = s * (1.f / COUT);
    float var  = sq * (1.f / COUT) - mean * mean;
    float inv  = rsqrtf(var + LN_EPS);
    float* dst = out + (size_t)row * COUT;
    dst[lane]      = fmaxf((v0 - mean) * inv * gamma[lane]      + beta[lane],      0.f);
    dst[lane + 32] = fmaxf((v1 - mean) * inv * gamma[lane + 32] + beta[lane + 32], 0.f);
    dst[lane + 64] = fmaxf((v2 - mean) * inv * gamma[lane + 64] + beta[lane + 64], 0.f);
}

// ---------------- launch ----------------------------------------------------------
extern "C" void kernel_launch(void* const* d_in, const int* in_sizes, int n_in,
                              void* d_out, int out_size) {
    const float* feats  = (const float*)d_in[0];
    const int*   coords = (const int*)  d_in[1];
    const float* weight = (const float*)d_in[2];
    const float* bias   = (const float*)d_in[3];
    const float* gamma  = (const float*)d_in[4];
    const float* beta   = (const float*)d_in[5];
    float* out = (float*)d_out;

    k_init       <<<4096, 256>>>();
    k_scatter    <<<NPTS / 256, 256>>>(coords);
    k_prep       <<<NPTS * 16 / 256, 256>>>(weight, feats);
    k_center_gemm<<<TILES_PER_K, 256>>>(coords, bias);   // 4th: ncu profiles this
    k_build_pairs<<<NPTS / 256, 256>>>(coords);
    k_make_tiles <<<1, 256>>>();
    k_offset_gemm<<<8192, 256>>>();
    k_ln_relu    <<<NPTS / 8, 256>>>(gamma, beta, out);
}

// round 17
// speedup vs baseline: 1.0405x; 1.0074x over previous
#include <cuda_runtime.h>
#include <cuda_fp16.h>

#define GRIDSZ 160
#define GRID3 (GRIDSZ*GRIDSZ*GRIDSZ)
#define NPTS 262144
#define CIN 64
#define COUT 96
#define TILE 64
#define TILES_PER_K 4096
#define LN_EPS 1e-5f
#define MAX_TILES (27 * TILES_PER_K)

// A smem row stride (words): 32 + 4 pad (36%32==4 -> conflict-free pattern)
#define RWA 36
// B smem row stride (words): 32 + 4 pad
#define RWB 36

// ---------------- scratch (static device globals; no allocation) ----------------
__device__ int    g_grid[GRID3];
__device__ int    g_win[NPTS];
__device__ int    g_cnt[27];
__device__ int2   g_pairs[27u * NPTS];
__device__ float  g_conv[(size_t)NPTS * COUT];
__device__ __half g_wprep[27 * 96 * 64];            // [k][n][cin], fp16, n-major
__device__ __half g_feat16[(size_t)NPTS * 64];      // fp16 features (single plane)
__device__ int    g_ntiles;
__device__ int2   g_tiles[MAX_TILES];               // (k, row_base)

// ---------------- helpers --------------------------------------------------------
__device__ __forceinline__ void mma16816h(float* c, unsigned a0, unsigned a1,
                                          unsigned a2, unsigned a3,
                                          unsigned b0, unsigned b1) {
    asm volatile(
        "mma.sync.aligned.m16n8k16.row.col.f32.f16.f16.f32 "
        "{%0,%1,%2,%3}, {%4,%5,%6,%7}, {%8,%9}, {%0,%1,%2,%3};"
        : "+f"(c[0]), "+f"(c[1]), "+f"(c[2]), "+f"(c[3])
        : "r"(a0), "r"(a1), "r"(a2), "r"(a3), "r"(b0), "r"(b1));
}

__device__ __forceinline__ void red_add4(float* addr, float a, float b, float c, float d) {
    asm volatile("red.global.add.v4.f32 [%0], {%1, %2, %3, %4};"
                 :: "l"(addr), "f"(a), "f"(b), "f"(c), "f"(d) : "memory");
}

// ---------------- 1) init grid to -1 ----------------------------------------------
__global__ void k_init() {
    int tid = blockIdx.x * blockDim.x + threadIdx.x;
    int4* g4 = (int4*)g_grid;
    const int n4 = GRID3 / 4;
    const int stride = gridDim.x * blockDim.x;
    int4 m1 = make_int4(-1, -1, -1, -1);
    for (int i = tid; i < n4; i += stride) g4[i] = m1;
}

// ---------------- 2) scatter (last-write-wins via atomicMax) + zero counters -----
__global__ void k_scatter(const int* __restrict__ coords) {
    int i = blockIdx.x * blockDim.x + threadIdx.x;
    if (blockIdx.x == 0 && threadIdx.x < 27) g_cnt[threadIdx.x] = 0;
    if (i < NPTS) {
        int z = coords[3*i+0], y = coords[3*i+1], x = coords[3*i+2];
        atomicMax(&g_grid[(z*GRIDSZ + y)*GRIDSZ + x], i);
    }
}

// ---------------- 3) prep: weights fp16 n-major + features fp16 ------------------
__global__ void k_prep(const float* __restrict__ w, const float* __restrict__ feats) {
    const int t = blockIdx.x * 256 + threadIdx.x;
    if (t < NPTS * 16) {
        float4 v = ((const float4*)feats)[t];
        __half2* dst = (__half2*)(g_feat16 + (size_t)t * 4);
        dst[0] = __floats2half2_rn(v.x, v.y);
        dst[1] = __floats2half2_rn(v.z, v.w);
    }
    if (t < 27 * CIN * COUT) {
        const int k = t / (CIN * COUT);
        const int r = t % (CIN * COUT);
        const int c = r / COUT;
        const int n = r % COUT;
        g_wprep[(k * 96 + n) * 64 + c] = __float2half_rn(w[t]);
    }
}

// ---------------- 4) symmetric pair build: winners probe 13 forward offsets ------
__global__ __launch_bounds__(256) void k_build_pairs(const int* __restrict__ coords) {
    __shared__ int s_cnt[13][8];
    __shared__ int s_baseF[13][8];
    __shared__ int s_baseM[13][8];

    const int tid  = threadIdx.x;
    const int p    = blockIdx.x * 256 + tid;
    const int warp = tid >> 5, lane = tid & 31;

    const int z = coords[3*p+0], y = coords[3*p+1], x = coords[3*p+2];
    const int cell = (z*GRIDSZ + y)*GRIDSZ + x;
    const int c = g_grid[cell];
    g_win[p] = c;
    const bool winner = (c == p);

    int nidx[13];
    #pragma unroll
    for (int k = 0; k < 13; ++k) {
        const int dz = k/9 - 1, dy = (k/3)%3 - 1, dx = k%3 - 1;
        int zz = z + dz, yy = y + dy, xx = x + dx;
        int ni = -1;
        if (winner && (unsigned)zz < GRIDSZ && (unsigned)yy < GRIDSZ && (unsigned)xx < GRIDSZ)
            ni = g_grid[(zz*GRIDSZ + yy)*GRIDSZ + xx];
        nidx[k] = ni;
    }

    #pragma unroll
    for (int k = 0; k < 13; ++k) {
        unsigned m = __ballot_sync(0xffffffffu, nidx[k] >= 0);
        if (lane == 0) s_cnt[k][warp] = __popc(m);
    }
    __syncthreads();

    if (tid < 13) {
        int cw[8], tot = 0;
        #pragma unroll
        for (int w = 0; w < 8; ++w) { cw[w] = s_cnt[tid][w]; tot += cw[w]; }
        int bF = tot ? atomicAdd(&g_cnt[tid],      tot) : 0;
        int bM = tot ? atomicAdd(&g_cnt[26 - tid], tot) : 0;
        #pragma unroll
        for (int w = 0; w < 8; ++w) {
            s_baseF[tid][w] = bF; bF += cw[w];
            s_baseM[tid][w] = bM; bM += cw[w];
        }
    }
    __syncthreads();

    #pragma unroll
    for (int k = 0; k < 13; ++k) {
        unsigned m = __ballot_sync(0xffffffffu, nidx[k] >= 0);
        if (nidx[k] >= 0) {
            int rank = __popc(m & ((1u << lane) - 1u));
            g_pairs[k * NPTS      + s_baseF[k][warp] + rank] = make_int2(p, nidx[k]);
            g_pairs[(26-k) * NPTS + s_baseM[k][warp] + rank] = make_int2(nidx[k], p);
        }
    }
}

// ---------------- 5) flatten non-empty tiles into a descriptor list ---------------
__global__ void k_make_tiles() {
    __shared__ int s_off[28];
    const int tid = threadIdx.x;
    if (tid < 32) {
        int cnt = (tid < 27) ? g_cnt[tid] : 0;
        int nt  = (cnt + TILE - 1) >> 6;
        int inc = nt;
        #pragma unroll
        for (int o = 1; o < 32; o <<= 1) {
            int v = __shfl_up_sync(0xffffffffu, inc, o);
            if (tid >= o) inc += v;
        }
        if (tid < 27) s_off[tid + 1] = inc;
        if (tid == 0) s_off[0] = 0;
        if (tid == 26) g_ntiles = inc;
    }
    __syncthreads();
    const int total = s_off[27];
    for (int t = tid; t < total; t += blockDim.x) {
        int k = 0;
        while (s_off[k + 1] <= t) ++k;
        g_tiles[t] = make_int2(k, (t - s_off[k]) * TILE);
    }
}

// ======================= shared GEMM-tile machinery (256 thr, 64-row tile) =======
// Direct gather from fp16 table: each thread copies 32B (2 x uint4), no converts.
__device__ __forceinline__ void gather_A_direct(unsigned* sAw, int ni, int tid) {
    const int row = tid >> 2, q = tid & 3;
    unsigned* d = &sAw[row * RWA + q * 8];
    if (ni >= 0) {
        const uint4* src = (const uint4*)(g_feat16 + (size_t)ni * 64) + q * 2;
        uint4 v0 = src[0], v1 = src[1];
        *(uint4*)(d)     = v0;
        *(uint4*)(d + 4) = v1;
    } else {
        uint4 z4 = make_uint4(0u, 0u, 0u, 0u);
        *(uint4*)(d)     = z4;
        *(uint4*)(d + 4) = z4;
    }
}

__device__ __forceinline__ void load_B(unsigned* sBw, int k, int tid) {
    const uint4* src = (const uint4*)&g_wprep[(size_t)k * 96 * 64];
    #pragma unroll
    for (int it = 0; it < 3; ++it) {
        int i = tid + it * 256;
        int n = i >> 3, q = i & 7;
        *(uint4*)&sBw[n * RWB + q * 4] = src[i];
    }
}

__device__ __forceinline__ void mma_mainloop(const unsigned* sAw, const unsigned* sBw,
                                             float acc[6][4], int lane, int wm, int wn) {
    const int g = lane >> 2, tg = lane & 3;
    const int r0 = wm * 16 + g, r1 = r0 + 8;
    #pragma unroll
    for (int kb = 0; kb < 4; ++kb) {
        const int kw = kb * 8 + tg;
        const unsigned a0 = sAw[r0 * RWA + kw],     a1 = sAw[r1 * RWA + kw];
        const unsigned a2 = sAw[r0 * RWA + kw + 4], a3 = sAw[r1 * RWA + kw + 4];
        #pragma unroll
        for (int nb = 0; nb < 6; ++nb) {
            const int n = wn * 48 + nb * 8 + g;
            const unsigned b0 = sBw[n * RWB + kw], b1 = sBw[n * RWB + kw + 4];
            mma16816h(acc[nb], a0, a1, a2, a3, b0, b1);
        }
    }
}

// ---------------- 6) center tap: dense GEMM, one barrier, float4 stores -----------
__global__ __launch_bounds__(256, 6) void k_center_gemm(const int* __restrict__ coords,
                                                        const float* __restrict__ bias) {
    __shared__ unsigned sAw[64 * RWA];
    __shared__ unsigned sBw[96 * RWB];

    const int tid  = threadIdx.x;
    const int base = blockIdx.x * TILE;

    {
        const int p = base + (tid >> 2);
        const int z = coords[3*p+0], y = coords[3*p+1], x = coords[3*p+2];
        const int ni = g_grid[(z*GRIDSZ + y)*GRIDSZ + x];   // winner (collision-aware)
        gather_A_direct(sAw, ni, tid);
    }
    load_B(sBw, 13, tid);
    __syncthreads();

    const int lane = tid & 31, wid = tid >> 5;
    const int wm = wid & 3, wn = wid >> 2;
    float acc[6][4];
    #pragma unroll
    for (int nb = 0; nb < 6; ++nb)
        #pragma unroll
        for (int c = 0; c < 4; ++c) acc[nb][c] = 0.f;

    mma_mainloop(sAw, sBw, acc, lane, wm, wn);

    const int g = lane >> 2, tg = lane & 3;
    const bool ev = (tg & 1) == 0;
    const int row0 = base + wm * 16 + g, row1 = row0 + 8;
    #pragma unroll
    for (int nb = 0; nb < 6; ++nb) {
        float s0 = ev ? acc[nb][2] : acc[nb][0];
        float s1 = ev ? acc[nb][3] : acc[nb][1];
        float r0 = __shfl_xor_sync(0xffffffffu, s0, 1);
        float r1 = __shfl_xor_sync(0xffffffffu, s1, 1);
        const int cb = wn * 48 + nb * 8 + (ev ? 2 * tg : 2 * (tg - 1));
        float4 b4 = *(const float4*)(bias + cb);
        if (ev) {
            *(float4*)(g_conv + (size_t)row0 * COUT + cb) =
                make_float4(acc[nb][0] + b4.x, acc[nb][1] + b4.y, r0 + b4.z, r1 + b4.w);
        } else {
            *(float4*)(g_conv + (size_t)row1 * COUT + cb) =
                make_float4(r0 + b4.x, r1 + b4.y, acc[nb][2] + b4.z, acc[nb][3] + b4.w);
        }
    }
}

// ---------------- 7) non-center taps: tile-list GEMM, 2 barriers/tile -------------
__global__ __launch_bounds__(256, 6) void k_offset_gemm() {
    __shared__ unsigned sAw[64 * RWA];
    __shared__ unsigned sBw[96 * RWB];

    const int tid   = threadIdx.x;
    const int lane  = tid & 31, wid = tid >> 5;
    const int wm    = wid & 3,  wn  = wid >> 2;
    const int total = g_ntiles;

    for (int t = blockIdx.x; t < total; t += gridDim.x) {
        const int2 td    = g_tiles[t];
        const int  k     = td.x;
        const int  rbase = td.y;
        const int  cnt   = g_cnt[k];

        {
            const int i = rbase + (tid >> 2);
            const int ni = (i < cnt) ? g_pairs[k * NPTS + i].y : -1;
            gather_A_direct(sAw, ni, tid);
        }
        load_B(sBw, k, tid);
        __syncthreads();

        float acc[6][4];
        #pragma unroll
        for (int nb = 0; nb < 6; ++nb)
            #pragma unroll
            for (int c = 0; c < 4; ++c) acc[nb][c] = 0.f;

        mma_mainloop(sAw, sBw, acc, lane, wm, wn);

        const int g = lane >> 2, tg = lane & 3;
        const bool ev = (tg & 1) == 0;
        const int i0 = rbase + wm * 16 + g, i1 = i0 + 8;
        const int op0 = (i0 < cnt) ? g_pairs[k * NPTS + i0].x : -1;
        const int op1 = (i1 < cnt) ? g_pairs[k * NPTS + i1].x : -1;
        #pragma unroll
        for (int nb = 0; nb < 6; ++nb) {
            float s0 = ev ? acc[nb][2] : acc[nb][0];
            float s1 = ev ? acc[nb][3] : acc[nb][1];
            float r0 = __shfl_xor_sync(0xffffffffu, s0, 1);
            float r1 = __shfl_xor_sync(0xffffffffu, s1, 1);
            const int cb = wn * 48 + nb * 8 + (ev ? 2 * tg : 2 * (tg - 1));
            if (ev) {
                if (op0 >= 0)
                    red_add4(g_conv + (size_t)op0 * COUT + cb,
                             acc[nb][0], acc[nb][1], r0, r1);
            } else {
                if (op1 >= 0)
                    red_add4(g_conv + (size_t)op1 * COUT + cb,
                             r0, r1, acc[nb][2], acc[nb][3]);
            }
        }
        __syncthreads();   // protect smem before next tile's gather
    }
}

// ---------------- 8) LayerNorm + ReLU (winner-row indirection) --------------------
__global__ __launch_bounds__(256) void k_ln_relu(const float* __restrict__ gamma,
                                                 const float* __restrict__ beta,
                                                 float* __restrict__ out) {
    const int row  = (blockIdx.x * 256 + threadIdx.x) >> 5;
    const int lane = threadIdx.x & 31;
    const int src_row = g_win[row];
    const float* src = g_conv + (size_t)src_row * COUT;
    float v0 = src[lane], v1 = src[lane + 32], v2 = src[lane + 64];
    float s  = v0 + v1 + v2;
    float sq = v0*v0 + v1*v1 + v2*v2;
    #pragma unroll
    for (int o = 16; o > 0; o >>= 1) {
        s  += __shfl_xor_sync(0xffffffffu, s,  o);
        sq += __shfl_xor_sync(0xffffffffu, sq, o);
    }
    float mean = s * (1.f / COUT);
    float var  = sq * (1.f / COUT) - mean * mean;
    float inv  = rsqrtf(var + LN_EPS);
    float* dst = out + (size_t)row * COUT;
    dst[lane]      = fmaxf((v0 - mean) * inv * gamma[lane]      + beta[lane],      0.f);
    dst[lane + 32] = fmaxf((v1 - mean) * inv * gamma[lane + 32] + beta[lane + 32], 0.f);
    dst[lane + 64] = fmaxf((v2 - mean) * inv * gamma[lane + 64] + beta[lane + 64], 0.f);
}

// ---------------- launch: fork-join pipeline over two streams ---------------------
extern "C" void kernel_launch(void* const* d_in, const int* in_sizes, int n_in,
                              void* d_out, int out_size) {
    const float* feats  = (const float*)d_in[0];
    const int*   coords = (const int*)  d_in[1];
    const float* weight = (const float*)d_in[2];
    const float* bias   = (const float*)d_in[3];
    const float* gamma  = (const float*)d_in[4];
    const float* beta   = (const float*)d_in[5];
    float* out = (float*)d_out;

    static cudaStream_t s1 = nullptr;
    static cudaEvent_t e0 = nullptr, ePrep = nullptr, eScat = nullptr, eTiles = nullptr;
    if (!s1) {
        cudaStreamCreateWithFlags(&s1, cudaStreamNonBlocking);
        cudaEventCreateWithFlags(&e0,     cudaEventDisableTiming);
        cudaEventCreateWithFlags(&ePrep,  cudaEventDisableTiming);
        cudaEventCreateWithFlags(&eScat,  cudaEventDisableTiming);
        cudaEventCreateWithFlags(&eTiles, cudaEventDisableTiming);
    }

    // fork side stream from the main (captured) stream
    cudaEventRecord(e0, 0);
    cudaStreamWaitEvent(s1, e0, 0);

    // side stream: feature/weight prep (independent of grid build)
    k_prep<<<NPTS * 16 / 256, 256, 0, s1>>>(weight, feats);
    cudaEventRecord(ePrep, s1);

    // main stream: grid init + scatter
    k_init   <<<4096, 256>>>();
    k_scatter<<<NPTS / 256, 256>>>(coords);
    cudaEventRecord(eScat, 0);

    // side stream: pair build + tile list (needs scatter, NOT prep/center)
    cudaStreamWaitEvent(s1, eScat, 0);
    k_build_pairs<<<NPTS / 256, 256, 0, s1>>>(coords);
    k_make_tiles <<<1, 256, 0, s1>>>();
    cudaEventRecord(eTiles, s1);

    // main stream: center GEMM (needs scatter + prep) — overlaps with build
    cudaStreamWaitEvent(0, ePrep, 0);
    k_center_gemm<<<TILES_PER_K, 256>>>(coords, bias);

    // main stream: offset GEMM (needs tiles + prep) then LN
    cudaStreamWaitEvent(0, eTiles, 0);
    k_offset_gemm<<<8192, 256>>>();
    k_ln_relu    <<<NPTS / 8, 256>>>(gamma, beta, out);
}